// round 1
// baseline (speedup 1.0000x reference)
#include <cuda_runtime.h>

// Winograd F(2x2,3x3) with constant filter FILT = [[0,-1,0],[-1,4,-1],[0,-1,0]].
// F = G @ FILT @ G^T (precomputed):
//   [[ 0.0, -0.5,  0.5,  0.0],
//    [-0.5,  0.0, -1.0, -0.5],
//    [ 0.5, -1.0,  2.0,  0.5],
//    [ 0.0, -0.5,  0.5,  0.0]]
// Per tile M (4x4): D = B M B^T ; Y = F .* D ; O = A Y A^T (2x2).
// Pure streaming: 64B in, 16B out per tile. HBM-bound.

__global__ __launch_bounds__(256) void winograd_kernel(
    const float4* __restrict__ in4,   // N*4 float4 (each tile = 4 consecutive float4)
    float4* __restrict__ out4,        // N float4 (2x2 output row-major)
    int n_tiles)
{
    int t = blockIdx.x * blockDim.x + threadIdx.x;
    if (t >= n_tiles) return;

    // Load tile: rows m0..m3, each a float4 (16 contiguous floats per tile)
    const float4 m0 = in4[4 * t + 0];
    const float4 m1 = in4[4 * t + 1];
    const float4 m2 = in4[4 * t + 2];
    const float4 m3 = in4[4 * t + 3];

    // T = B @ M   (rows: t0 = m0 - m2; t1 = m1 + m2; t2 = m2 - m1; t3 = m1 - m3)
    float t0x = m0.x - m2.x, t0y = m0.y - m2.y, t0z = m0.z - m2.z, t0w = m0.w - m2.w;
    float t1x = m1.x + m2.x, t1y = m1.y + m2.y, t1z = m1.z + m2.z, t1w = m1.w + m2.w;
    float t2x = m2.x - m1.x, t2y = m2.y - m1.y, t2z = m2.z - m1.z, t2w = m2.w - m1.w;
    float t3x = m1.x - m3.x, t3y = m1.y - m3.y, t3z = m1.z - m3.z, t3w = m1.w - m3.w;

    // D = T @ B^T   (per row t=[a,b,c,d]: [a-c, b+c, c-b, b-d])
    float d00 = t0x - t0z, d01 = t0y + t0z, d02 = t0z - t0y, d03 = t0y - t0w;
    float d10 = t1x - t1z, d11 = t1y + t1z, d12 = t1z - t1y, d13 = t1y - t1w;
    float d20 = t2x - t2z, d21 = t2y + t2z, d22 = t2z - t2y, d23 = t2y - t2w;
    float d30 = t3x - t3z, d31 = t3y + t3z, d32 = t3z - t3y, d33 = t3y - t3w;
    (void)d00; (void)d30; (void)d33; (void)d03; // F zeros these

    // Y = F .* D  (F zeros at (0,0),(0,3),(1,1),(3,0),(3,3))
    float y01 = -0.5f * d01;
    float y02 =  0.5f * d02;
    float y10 = -0.5f * d10;
    float y12 = -d12;
    float y13 = -0.5f * d13;
    float y20 =  0.5f * d20;
    float y21 = -d21;
    float y22 =  2.0f * d22;
    float y23 =  0.5f * d23;
    float y31 = -0.5f * d31;
    float y32 =  0.5f * d32;
    // y00 = y03 = y11 = y30 = y33 = 0

    // Z = A @ Y   (z0 = y0 + y1 + y2 ; z1 = y1 - y2 - y3)
    float z00 = y10 + y20;              // y00 = 0
    float z01 = y01 + y21;              // y11 = 0
    float z02 = y02 + y12 + y22;
    float z03 = y13 + y23;              // y03 = 0
    float z10 = y10 - y20;              // y30 = 0 (nothing to subtract beyond y20)
    float z11 = -y21 - y31;             // y11 = 0
    float z12 = y12 - y22 - y32;
    float z13 = y13 - y23;              // y33 = 0

    // O = Z @ A^T  (per row z=[p,q,r,s]: [p+q+r, q-r-s])
    float4 o;
    o.x = z00 + z01 + z02;
    o.y = z01 - z02 - z03;
    o.z = z10 + z11 + z12;
    o.w = z11 - z12 - z13;

    out4[t] = o;
}

extern "C" void kernel_launch(void* const* d_in, const int* in_sizes, int n_in,
                              void* d_out, int out_size) {
    const float* x = (const float*)d_in[0];
    float* out = (float*)d_out;
    int n_tiles = in_sizes[0] / 16;   // each tile is 16 floats

    const int threads = 256;
    int blocks = (n_tiles + threads - 1) / threads;
    winograd_kernel<<<blocks, threads>>>(
        (const float4*)x, (float4*)out, n_tiles);
}

// round 2
// speedup vs baseline: 1.2982x; 1.2982x over previous
#include <cuda_runtime.h>

// Winograd F(2x2,3x3) with constant filter [[0,-1,0],[-1,4,-1],[0,-1,0]].
// The full pipeline O = A.(F∘(B M Bᵀ)).Aᵀ algebraically equals the direct 3x3
// Laplacian convolution of the 4x4 tile, which is row-separable:
//   row r = (a,b,c,d):  x_r = (-b, -c)          (contributes to rows r and r-2 of O? no:)
//                       y_r = (4b-a-c, 4c-b-d)
//   O_row0 = x_0 + y_1 + x_2
//   O_row1 = x_1 + y_2 + x_3
//
// Layout: one lane per input row (float4), fully coalesced LDG.128.
// 4-lane groups assemble a tile via 4x SHFL.32. Lanes r<2 write float2 outputs
// (contiguous 128B per warp). L1 wavefronts per 32 tiles: 16 LDG + 16 SHFL +
// 4 STG = 36 (vs 68 before) -> DRAM-bound.

__global__ __launch_bounds__(256) void winograd_kernel(
    const float4* __restrict__ in4,   // n4 float4s (4 per tile, row-major)
    float2* __restrict__ out2,        // 2 float2 per tile (rows of 2x2 output)
    int n4)
{
    int j = blockIdx.x * blockDim.x + threadIdx.x;   // global float4 (row) index
    bool valid = j < n4;

    float4 m = valid ? in4[j] : make_float4(0.f, 0.f, 0.f, 0.f);

    // Per-row contributions
    float x0 = -m.y;
    float x1 = -m.z;
    float y0 = fmaf(4.0f, m.y, -m.x) - m.z;   // 4b - a - c
    float y1 = fmaf(4.0f, m.z, -m.y) - m.w;   // 4c - b - d

    // Combine within 4-lane tile groups (r = lane & 3):
    //   z(r)   = x(r) + y(r+1)
    //   O_row  = z(r) + x(r+2)      -> valid at r = 0 (row0) and r = 1 (row1)
    const unsigned FULL = 0xFFFFFFFFu;
    float z0 = x0 + __shfl_down_sync(FULL, y0, 1);
    float z1 = x1 + __shfl_down_sync(FULL, y1, 1);
    float o0 = z0 + __shfl_down_sync(FULL, x0, 2);
    float o1 = z1 + __shfl_down_sync(FULL, x1, 2);

    int r = j & 3;
    if (valid && r < 2) {
        // tile = j >> 2 ; output row r of that tile
        out2[((j >> 2) << 1) | r] = make_float2(o0, o1);
    }
}

extern "C" void kernel_launch(void* const* d_in, const int* in_sizes, int n_in,
                              void* d_out, int out_size) {
    const float* x = (const float*)d_in[0];
    float* out = (float*)d_out;
    int n4 = in_sizes[0] / 4;   // number of float4 rows (4 per tile)

    const int threads = 256;
    int blocks = (n4 + threads - 1) / threads;
    winograd_kernel<<<blocks, threads>>>(
        (const float4*)x, (float2*)out, n4);
}

// round 3
// speedup vs baseline: 1.6103x; 1.2404x over previous
#include <cuda_runtime.h>

// Winograd F(2x2,3x3) with constant Laplacian filter == direct 3x3 conv of each
// 4x4 tile; row-separable:
//   row r = (a,b,c,d):  x_r = (-b, -c),  y_r = (4b-a-c, 4c-b-d)
//   O_row0 = x_0 + y_1 + x_2 ;  O_row1 = x_1 + y_2 + x_3
//
// One lane per input row (float4, coalesced LDG.128); 4-lane groups assemble a
// tile via SHFL. R2 showed DRAM stuck at 69% with MLP=1/thread -> this version
// batches ITERS=4 independent loads per thread (front-batched LDG.128 x4) to
// cover DRAM latency, with streaming cache hints (data touched once).

#define ITERS 4

__global__ __launch_bounds__(256) void winograd_kernel(
    const float4* __restrict__ in4,   // n4 float4s (4 per tile, row-major)
    float2* __restrict__ out2,        // 2 float2 per tile
    int n4)
{
    // Block owns a contiguous segment of ITERS*256 rows; thread t handles
    // rows seg + t + k*256. lane&3 == row-within-tile for every k.
    int seg = blockIdx.x * (blockDim.x * ITERS);
    int tid = threadIdx.x;

    float4 m[ITERS];
    int    j[ITERS];

    // Front-batch independent loads (MLP_p1 = ITERS)
    #pragma unroll
    for (int k = 0; k < ITERS; k++) {
        j[k] = seg + k * 256 + tid;
        m[k] = (j[k] < n4) ? __ldcs(&in4[j[k]])
                           : make_float4(0.f, 0.f, 0.f, 0.f);
    }

    const unsigned FULL = 0xFFFFFFFFu;
    int r = tid & 3;

    #pragma unroll
    for (int k = 0; k < ITERS; k++) {
        float x0 = -m[k].y;
        float x1 = -m[k].z;
        float y0 = fmaf(4.0f, m[k].y, -m[k].x) - m[k].z;   // 4b - a - c
        float y1 = fmaf(4.0f, m[k].z, -m[k].y) - m[k].w;   // 4c - b - d

        float z0 = x0 + __shfl_down_sync(FULL, y0, 1);
        float z1 = x1 + __shfl_down_sync(FULL, y1, 1);
        float o0 = z0 + __shfl_down_sync(FULL, x0, 2);
        float o1 = z1 + __shfl_down_sync(FULL, x1, 2);

        if (r < 2 && j[k] < n4) {
            // tile = j>>2, output row r of that tile
            __stcs(&out2[((j[k] >> 2) << 1) | r], make_float2(o0, o1));
        }
    }
}

extern "C" void kernel_launch(void* const* d_in, const int* in_sizes, int n_in,
                              void* d_out, int out_size) {
    const float* x = (const float*)d_in[0];
    float* out = (float*)d_out;
    int n4 = in_sizes[0] / 4;   // number of float4 rows (4 per tile)

    const int threads = 256;
    int rows_per_block = threads * ITERS;
    int blocks = (n4 + rows_per_block - 1) / rows_per_block;
    winograd_kernel<<<blocks, threads>>>(
        (const float4*)x, (float2*)out, n4);
}